// round 17
// baseline (speedup 1.0000x reference)
#include <cuda_runtime.h>

#define K_DIM 7168
#define E_DIM 256
#define BM 112            // 16 warps x 7 m-rows -> 147 m-tiles -> 294 CTAs ~ 2 clean waves
#define BN 128
#define BK 32
#define KC_TILES 10       // Eigen kc=320 floats = 10 tiles of BK=32

// packed f32x2 FMA (Blackwell): per-component IEEE rn fma
__device__ __forceinline__ unsigned long long ffma2(unsigned long long a,
                                                    unsigned long long b,
                                                    unsigned long long c) {
    unsigned long long d;
    asm("fma.rn.f32x2 %0, %1, %2, %3;" : "=l"(d) : "l"(a), "l"(b), "l"(c));
    return d;
}

__device__ __forceinline__ unsigned long long fadd2(unsigned long long a,
                                                    unsigned long long b) {
    unsigned long long d;
    asm("add.rn.f32x2 %0, %1, %2;" : "=l"(d) : "l"(a), "l"(b));
    return d;
}

__device__ __forceinline__ unsigned long long dup_f32(float a) {
    unsigned long long p;
    asm("mov.b64 %0, {%1, %1};" : "=l"(p) : "r"(__float_as_uint(a)));
    return p;
}

// C[t, e] = sum_k A[t,k] * W[e,k] — fp32, Eigen-blocked accumulation order:
// c = ((0 + S_0) + S_1) + ... ; S_b = ascending-k fma partial over kc=320 block
// (last block = 128). BIT-EXACT match to XLA:CPU Eigen gemm — do not reorder.
//
// R16 skeleton (512 threads, 16 warps, BK=32, natural smem, float4 loaders,
// m-packed accumulators) with BM=128 -> 112: each warp covers 7 m-rows
// (3 packed pairs + 1 scalar row). 147 x 2 = 294 CTAs -> two clean waves on
// 148 SMs, each tile 112/128 the work -> makespan 2 x 0.917 T vs R16's 2 x T.
// A rows live in 8-wide per-warp slots (col = warp*8 + row%7) for alignment.
__global__ __launch_bounds__(512)
void moe_gemm_kernel(const float* __restrict__ A,
                     const float* __restrict__ W,
                     float* __restrict__ C, int T) {
    __shared__ float As[2][BK][128];   // 8-wide slot per warp, col 7 of each slot unused
    __shared__ float Bs[2][BK][BN];

    const int tid = threadIdx.x;
    const int tx = tid & 31;   // expert direction: 4 experts per thread
    const int ty = tid >> 5;   // warp id: 7 tokens per thread
    const int m0 = blockIdx.x * BM;
    const int n0 = blockIdx.y * BN;

    // A loader: threads 0..447: 4 threads per row, 8 floats (2x float4) each
    const int alr = tid >> 2;              // row 0..111 (valid when tid < 448)
    const int alc = (tid & 3) * 8;         // K offset 0,8,16,24
    const bool aload = (tid < 448);
    const int acol = (alr / 7) * 8 + (alr % 7);   // aligned slot column
    int agrow = m0 + alr;                  // clamp for last partial tile
    if (agrow > T - 1) agrow = T - 1;
    const float* Abase = A + (size_t)agrow * K_DIM + alc;

    // B loader: 4 threads per row, 8 floats (2x float4) each (128 rows x 32 k)
    const int blr = tid >> 2;
    const int blc = (tid & 3) * 8;
    const float* Wbase = W + (size_t)(n0 + blr) * K_DIM + blc;

    // acc[n][p]: expert n0+tx*4+n, m-pair (m0+ty*7+2p, +2p+1), p=0..2
    // acc7[n]:   expert n, scalar row m0+ty*7+6
    unsigned long long acc[4][3], bac[4][3];
    float acc7[4], bac7[4];
#pragma unroll
    for (int n = 0; n < 4; ++n) {
#pragma unroll
        for (int p = 0; p < 3; ++p) { acc[n][p] = 0ull; bac[n][p] = 0ull; }
        acc7[n] = 0.0f; bac7[n] = 0.0f;
    }

    float4 aP0, aP1;
    if (aload) {
        aP0 = *reinterpret_cast<const float4*>(Abase);
        aP1 = *reinterpret_cast<const float4*>(Abase + 4);
    }
    float4 bP0 = *reinterpret_cast<const float4*>(Wbase);
    float4 bP1 = *reinterpret_cast<const float4*>(Wbase + 4);

    const int nIter = K_DIM / BK;  // 224
    for (int kt = 0; kt < nIter; ++kt) {
        const int buf = kt & 1;
        if (aload) {
            As[buf][alc + 0][acol] = aP0.x; As[buf][alc + 1][acol] = aP0.y;
            As[buf][alc + 2][acol] = aP0.z; As[buf][alc + 3][acol] = aP0.w;
            As[buf][alc + 4][acol] = aP1.x; As[buf][alc + 5][acol] = aP1.y;
            As[buf][alc + 6][acol] = aP1.z; As[buf][alc + 7][acol] = aP1.w;
        }
        Bs[buf][blc + 0][blr] = bP0.x; Bs[buf][blc + 1][blr] = bP0.y;
        Bs[buf][blc + 2][blr] = bP0.z; Bs[buf][blc + 3][blr] = bP0.w;
        Bs[buf][blc + 4][blr] = bP1.x; Bs[buf][blc + 5][blr] = bP1.y;
        Bs[buf][blc + 6][blr] = bP1.z; Bs[buf][blc + 7][blr] = bP1.w;
        __syncthreads();

        // prefetch next tile from global (hidden under compute below)
        if (kt + 1 < nIter) {
            if (aload) {
                const float* an = Abase + (size_t)(kt + 1) * BK;
                aP0 = *reinterpret_cast<const float4*>(an);
                aP1 = *reinterpret_cast<const float4*>(an + 4);
            }
            const float* wn = Wbase + (size_t)(kt + 1) * BK;
            bP0 = *reinterpret_cast<const float4*>(wn);
            bP1 = *reinterpret_cast<const float4*>(wn + 4);
        }

#pragma unroll
        for (int k = 0; k < BK; ++k) {
            // A: warp slot = 8 floats: 3 natural packed pairs + 1 scalar
            ulonglong2 q01 = *reinterpret_cast<const ulonglong2*>(&As[buf][k][ty * 8]);
            unsigned long long q2 =
                *reinterpret_cast<const unsigned long long*>(&As[buf][k][ty * 8 + 4]);
            float a6 = As[buf][k][ty * 8 + 6];
            // B: 4 expert scalars, 1 LDS.128, 4 dups
            float4 bf = *reinterpret_cast<const float4*>(&Bs[buf][k][tx * 4]);
            unsigned long long pb0 = dup_f32(bf.x);
            unsigned long long pb1 = dup_f32(bf.y);
            unsigned long long pb2 = dup_f32(bf.z);
            unsigned long long pb3 = dup_f32(bf.w);
            bac[0][0] = ffma2(q01.x, pb0, bac[0][0]);
            bac[0][1] = ffma2(q01.y, pb0, bac[0][1]);
            bac[0][2] = ffma2(q2,    pb0, bac[0][2]);
            bac7[0]   = __fmaf_rn(a6, bf.x, bac7[0]);
            bac[1][0] = ffma2(q01.x, pb1, bac[1][0]);
            bac[1][1] = ffma2(q01.y, pb1, bac[1][1]);
            bac[1][2] = ffma2(q2,    pb1, bac[1][2]);
            bac7[1]   = __fmaf_rn(a6, bf.y, bac7[1]);
            bac[2][0] = ffma2(q01.x, pb2, bac[2][0]);
            bac[2][1] = ffma2(q01.y, pb2, bac[2][1]);
            bac[2][2] = ffma2(q2,    pb2, bac[2][2]);
            bac7[2]   = __fmaf_rn(a6, bf.z, bac7[2]);
            bac[3][0] = ffma2(q01.x, pb3, bac[3][0]);
            bac[3][1] = ffma2(q01.y, pb3, bac[3][1]);
            bac[3][2] = ffma2(q2,    pb3, bac[3][2]);
            bac7[3]   = __fmaf_rn(a6, bf.w, bac7[3]);
        }

        // Eigen kc=320 block boundary: c += S_b; S_b = 0
        if (((kt + 1) % KC_TILES) == 0) {
#pragma unroll
            for (int n = 0; n < 4; ++n) {
#pragma unroll
                for (int p = 0; p < 3; ++p) {
                    acc[n][p] = fadd2(acc[n][p], bac[n][p]);
                    bac[n][p] = 0ull;
                }
                acc7[n] = __fadd_rn(acc7[n], bac7[n]);
                bac7[n] = 0.0f;
            }
        }
    }

    // final (remainder 128-wide) block flush
#pragma unroll
    for (int n = 0; n < 4; ++n) {
#pragma unroll
        for (int p = 0; p < 3; ++p) acc[n][p] = fadd2(acc[n][p], bac[n][p]);
        acc7[n] = __fadd_rn(acc7[n], bac7[n]);
    }

    // epilogue: pair p component c -> row m0+ty*7+2p+c; scalar -> row +6
#pragma unroll
    for (int p = 0; p < 3; ++p) {
        float2 e0 = *reinterpret_cast<float2*>(&acc[0][p]);
        float2 e1 = *reinterpret_cast<float2*>(&acc[1][p]);
        float2 e2 = *reinterpret_cast<float2*>(&acc[2][p]);
        float2 e3 = *reinterpret_cast<float2*>(&acc[3][p]);
        int mb = m0 + ty * 7 + p * 2;
        if (mb < T) {
            float* c0 = C + (size_t)mb * E_DIM + n0 + tx * 4;
            *reinterpret_cast<float4*>(c0) = make_float4(e0.x, e1.x, e2.x, e3.x);
        }
        if (mb + 1 < T) {
            float* c1 = C + (size_t)(mb + 1) * E_DIM + n0 + tx * 4;
            *reinterpret_cast<float4*>(c1) = make_float4(e0.y, e1.y, e2.y, e3.y);
        }
    }
    {
        int m6 = m0 + ty * 7 + 6;
        if (m6 < T) {
            float* c6 = C + (size_t)m6 * E_DIM + n0 + tx * 4;
            *reinterpret_cast<float4*>(c6) =
                make_float4(acc7[0], acc7[1], acc7[2], acc7[3]);
        }
    }
}

// XLA EmitFastTanh replica — UNFUSED mul/add Horner (CPU LLVM does not
// contract), IEEE fdiv, clamp +-7.90531110763549805, |x|<0.0004 -> x.
__device__ __forceinline__ float xla_tanhf_nofma(float x) {
    float xc = fminf(fmaxf(x, -7.90531110763549805f), 7.90531110763549805f);
    float x2 = __fmul_rn(xc, xc);
    float np = -2.76076847742355e-16f;
    np = __fadd_rn(__fmul_rn(x2, np),  2.00018790482477e-13f);
    np = __fadd_rn(__fmul_rn(x2, np), -8.60467152213735e-11f);
    np = __fadd_rn(__fmul_rn(x2, np),  5.12229709037114e-08f);
    np = __fadd_rn(__fmul_rn(x2, np),  1.48572235717979e-05f);
    np = __fadd_rn(__fmul_rn(x2, np),  6.37261928875436e-04f);
    np = __fadd_rn(__fmul_rn(x2, np),  4.89352455891786e-03f);
    float num = __fmul_rn(xc, np);
    float dp = 1.19825839466702e-06f;
    dp = __fadd_rn(__fmul_rn(x2, dp), 1.18534705686654e-04f);
    dp = __fadd_rn(__fmul_rn(x2, dp), 2.26843463243900e-03f);
    dp = __fadd_rn(__fmul_rn(x2, dp), 4.89352518554385e-03f);
    float r = __fdiv_rn(num, dp);
    return (fabsf(x) < 0.0004f) ? x : r;
}

// XLA logistic: 0.5 + 0.5 * tanh(0.5 * x), unfused.
__device__ __forceinline__ float sigmoid_xla(float x) {
    float t = xla_tanhf_nofma(__fmul_rn(0.5f, x));
    return __fadd_rn(0.5f, __fmul_rn(0.5f, t));
}

// one warp per token
__global__ void moe_router_kernel(const float* __restrict__ logits,
                                  float* __restrict__ outW,
                                  float* __restrict__ outI, int T) {
    const unsigned FULL = 0xFFFFFFFFu;
    int warp = (blockIdx.x * blockDim.x + threadIdx.x) >> 5;
    int lane = threadIdx.x & 31;
    if (warp >= T) return;

    const float* row = logits + (size_t)warp * E_DIM;
    float4 v0 = *reinterpret_cast<const float4*>(row + lane * 8);
    float4 v1 = *reinterpret_cast<const float4*>(row + lane * 8 + 4);

    float s[8];
    s[0] = sigmoid_xla(v0.x); s[1] = sigmoid_xla(v0.y);
    s[2] = sigmoid_xla(v0.z); s[3] = sigmoid_xla(v0.w);
    s[4] = sigmoid_xla(v1.x); s[5] = sigmoid_xla(v1.y);
    s[6] = sigmoid_xla(v1.z); s[7] = sigmoid_xla(v1.w);

    // group sum over 32 experts (butterfly tree)
    float f[8];
#pragma unroll
    for (int j = 0; j < 8; ++j)
        f[j] = s[j] + __shfl_xor_sync(FULL, s[j], 2);
    float g[8];
#pragma unroll
    for (int j = 0; j < 8; ++j)
        g[j] = f[j] + __shfl_xor_sync(FULL, f[j], 1);
    float h0 = g[0] + g[4];
    float h1 = g[1] + g[5];
    float h2 = g[2] + g[6];
    float h3 = g[3] + g[7];
    float p0 = h0 + h2;
    float p1 = h1 + h3;
    float mygs = p0 + p1;     // group sum for group (lane>>2)
    int myg = lane >> 2;

    // rank of my group among 8 groups (ties -> lower index, jax top_k)
    int rank = 0;
#pragma unroll
    for (int h = 0; h < 8; ++h) {
        float gh = __shfl_sync(FULL, mygs, h * 4);
        if (h != myg && (gh > mygs || (gh == mygs && h < myg))) rank++;
    }
    bool sel = (rank < 4);

    float ms[8];
#pragma unroll
    for (int j = 0; j < 8; ++j) ms[j] = sel ? s[j] : 0.0f;

    float topv[8];
    int topi[8];
#pragma unroll
    for (int it = 0; it < 8; ++it) {
        float bv = -1.0f;
        int bi = 0;
#pragma unroll
        for (int j = 0; j < 8; ++j) {
            if (ms[j] > bv) { bv = ms[j]; bi = lane * 8 + j; }
        }
#pragma unroll
        for (int off = 16; off; off >>= 1) {
            float ov = __shfl_xor_sync(FULL, bv, off);
            int oi = __shfl_xor_sync(FULL, bi, off);
            if (ov > bv || (ov == bv && oi < bi)) { bv = ov; bi = oi; }
        }
        topv[it] = bv;
        topi[it] = bi;
        if ((bi >> 3) == lane) ms[bi & 7] = -1.0f;
    }

    float denom = 0.f;
#pragma unroll
    for (int it = 0; it < 8; ++it) denom += topv[it];
    denom = fmaxf(denom, 1e-12f);

    if (lane < 8) {
        outW[(size_t)warp * 8 + lane] = __fdiv_rn(topv[lane], denom);
        outI[(size_t)warp * 8 + lane] = (float)topi[lane];
    }
}

extern "C" void kernel_launch(void* const* d_in, const int* in_sizes, int n_in,
                              void* d_out, int out_size) {
    const float* H = (const float*)d_in[0];   // [T, 7168] fp32
    const float* W = (const float*)d_in[1];   // [256, 7168] fp32
    float* out = (float*)d_out;

    int T = in_sizes[0] / K_DIM;

    // output layout: [T*8 weights][T*8 indices][T*256 logits]
    float* outW = out;
    float* outI = out + (size_t)T * 8;
    float* logits = out + (size_t)T * 16;

    // 147 m-tiles x 2 n-tiles = 294 CTAs -> two clean waves on 148 SMs
    dim3 grid((T + BM - 1) / BM, E_DIM / BN);
    moe_gemm_kernel<<<grid, 512>>>(H, W, logits, T);

    int warps = T;
    int threads = 256;
    int blocks = (warps * 32 + threads - 1) / threads;
    moe_router_kernel<<<blocks, threads>>>(logits, outW, outI, T);
}